// round 1
// baseline (speedup 1.0000x reference)
#include <cuda_runtime.h>
#include <cstddef>

#define DIM      64
#define CBK      4096
#define MAXM     32768
#define BM       128
#define BN       128
#define TM       8
#define TN       8
#define NTHREADS 256

// Scratch (no dynamic allocation allowed)
__device__ float g_hn[CBK];     // 0.5 * ||e_k||^2
__device__ int   g_idx[MAXM];   // argmax index per row

// ---------------------------------------------------------------------------
// Precompute half squared norms of codebook rows.
// ---------------------------------------------------------------------------
__global__ void hn_kernel(const float* __restrict__ embed) {
    int c = blockIdx.x * blockDim.x + threadIdx.x;
    if (c < CBK) {
        const float4* e = reinterpret_cast<const float4*>(embed + (size_t)c * DIM);
        float s = 0.f;
#pragma unroll
        for (int i = 0; i < DIM / 4; i++) {
            float4 v = e[i];
            s += v.x * v.x + v.y * v.y + v.z * v.z + v.w * v.w;
        }
        g_hn[c] = 0.5f * s;
    }
}

// ---------------------------------------------------------------------------
// Fused GEMM (x @ embed^T) + running row-argmax of (x.e - 0.5*||e||^2).
// Block tile: 128 rows x 128 codes, K = 64 (full depth, single pass).
// 256 threads (16x16), each owns an 8x8 micro-tile.
// SMEM tiles stored k-major for conflict-free float4 LDS in the mainloop.
// ---------------------------------------------------------------------------
__global__ __launch_bounds__(NTHREADS, 2)
void vq_argmax_kernel(const float* __restrict__ x,
                      const float* __restrict__ embed,
                      float* __restrict__ out_ind)  // may be nullptr
{
    extern __shared__ float smem[];
    float* x_s  = smem;                 // [DIM][BM]  (k-major)
    float* e_s  = smem + DIM * BM;      // [DIM][BN]  (k-major)
    float* hn_s = smem + 2 * DIM * BM;  // [CBK]

    const int t  = threadIdx.x;
    const int tx = t & 15;
    const int ty = t >> 4;
    const int rowBase = blockIdx.x * BM;

    // ---- Load x tile, transposed to k-major -------------------------------
    // 128 rows * 16 float4 = 2048 float4-slots; 8 per thread.
#pragma unroll
    for (int it = 0; it < (BM * (DIM / 4)) / NTHREADS; it++) {
        int idx = t + it * NTHREADS;
        int k4  = idx >> 7;        // 0..15
        int row = idx & (BM - 1);  // 0..127 (consecutive across lanes -> STS conflict-free)
        float4 v = *reinterpret_cast<const float4*>(
            x + (size_t)(rowBase + row) * DIM + k4 * 4);
        x_s[(k4 * 4 + 0) * BM + row] = v.x;
        x_s[(k4 * 4 + 1) * BM + row] = v.y;
        x_s[(k4 * 4 + 2) * BM + row] = v.z;
        x_s[(k4 * 4 + 3) * BM + row] = v.w;
    }

    // ---- Load all 4096 half-norms into SMEM (coalesced float4) ------------
#pragma unroll
    for (int it = 0; it < CBK / (NTHREADS * 4); it++) {
        int idx = (t + it * NTHREADS) * 4;
        *reinterpret_cast<float4*>(&hn_s[idx]) =
            *reinterpret_cast<const float4*>(&g_hn[idx]);
    }

    float best[TM];
    int   bidx[TM];
#pragma unroll
    for (int i = 0; i < TM; i++) { best[i] = -3.402823466e38f; bidx[i] = 0; }

    // ---- Mainloop over 32 N-tiles -----------------------------------------
    for (int nt = 0; nt < CBK / BN; nt++) {
        __syncthreads();  // protect e_s of previous iteration

        // Load e tile, transposed to k-major
#pragma unroll
        for (int it = 0; it < (BN * (DIM / 4)) / NTHREADS; it++) {
            int idx = t + it * NTHREADS;
            int k4  = idx >> 7;
            int col = idx & (BN - 1);
            float4 v = *reinterpret_cast<const float4*>(
                embed + (size_t)(nt * BN + col) * DIM + k4 * 4);
            e_s[(k4 * 4 + 0) * BN + col] = v.x;
            e_s[(k4 * 4 + 1) * BN + col] = v.y;
            e_s[(k4 * 4 + 2) * BN + col] = v.z;
            e_s[(k4 * 4 + 3) * BN + col] = v.w;
        }
        __syncthreads();

        float acc[TM][TN];
#pragma unroll
        for (int i = 0; i < TM; i++)
#pragma unroll
            for (int j = 0; j < TN; j++) acc[i][j] = 0.f;

#pragma unroll 8
        for (int k = 0; k < DIM; k++) {
            float a[TM], b[TN];
            *reinterpret_cast<float4*>(&a[0]) =
                *reinterpret_cast<const float4*>(&x_s[k * BM + ty * TM]);
            *reinterpret_cast<float4*>(&a[4]) =
                *reinterpret_cast<const float4*>(&x_s[k * BM + ty * TM + 4]);
            *reinterpret_cast<float4*>(&b[0]) =
                *reinterpret_cast<const float4*>(&e_s[k * BN + tx * TN]);
            *reinterpret_cast<float4*>(&b[4]) =
                *reinterpret_cast<const float4*>(&e_s[k * BN + tx * TN + 4]);
#pragma unroll
            for (int i = 0; i < TM; i++)
#pragma unroll
                for (int j = 0; j < TN; j++)
                    acc[i][j] = fmaf(a[i], b[j], acc[i][j]);
        }

        // Epilogue: fold this tile into the running argmax
        const int colBase = nt * BN + tx * TN;
#pragma unroll
        for (int j = 0; j < TN; j++) {
            float hn = hn_s[colBase + j];
#pragma unroll
            for (int i = 0; i < TM; i++) {
                float s = acc[i][j] - hn;
                if (s > best[i]) { best[i] = s; bidx[i] = colBase + j; }
            }
        }
    }

    // ---- Cross-thread reduction (16 partials per row) ---------------------
    __syncthreads();
    float* rv = smem;                              // [BM][16]
    int*   ri = reinterpret_cast<int*>(smem + BM * 16);
#pragma unroll
    for (int i = 0; i < TM; i++) {
        int row = ty * TM + i;
        rv[row * 16 + tx] = best[i];
        ri[row * 16 + tx] = bidx[i];
    }
    __syncthreads();

    if (t < BM) {
        float bv = rv[t * 16];
        int   bi = ri[t * 16];
#pragma unroll
        for (int j = 1; j < 16; j++) {
            float v = rv[t * 16 + j];
            int   ii = ri[t * 16 + j];
            if (v > bv || (v == bv && ii < bi)) { bv = v; bi = ii; }
        }
        int grow = rowBase + t;
        g_idx[grow] = bi;
        if (out_ind) out_ind[grow] = (float)bi;
    }
}

// ---------------------------------------------------------------------------
// Gather: quantize[row] = embed[idx[row]]  (float4 vectorized)
// ---------------------------------------------------------------------------
__global__ void gather_kernel(const float* __restrict__ embed,
                              float* __restrict__ out, int M) {
    int tid = blockIdx.x * blockDim.x + threadIdx.x;
    if (tid < M * (DIM / 4)) {
        int row = tid >> 4;
        int c   = tid & 15;
        int idx = g_idx[row];
        *reinterpret_cast<float4*>(out + (size_t)row * DIM + c * 4) =
            *reinterpret_cast<const float4*>(embed + (size_t)idx * DIM + c * 4);
    }
}

// Zero any tail of the output buffer we don't semantically own.
__global__ void fill_kernel(float* __restrict__ out, int start, int end) {
    int i = start + blockIdx.x * blockDim.x + threadIdx.x;
    if (i < end) out[i] = 0.f;
}

// ---------------------------------------------------------------------------
extern "C" void kernel_launch(void* const* d_in, const int* in_sizes, int n_in,
                              void* d_out, int out_size) {
    const float* x     = (const float*)d_in[0];   // [8,4096,64] f32
    const float* embed = (const float*)d_in[1];   // [4096,64]   f32
    float* out = (float*)d_out;

    const int M = in_sizes[0] / DIM;  // 32768

    // 1) Half-norms of codebook
    hn_kernel<<<(CBK + 255) / 256, 256>>>(embed);

    // 2) Fused GEMM + argmax
    size_t smem_bytes = (size_t)(2 * DIM * BM + CBK) * sizeof(float);  // 80 KB
    cudaFuncSetAttribute(vq_argmax_kernel,
                         cudaFuncAttributeMaxDynamicSharedMemorySize,
                         (int)smem_bytes);
    float* out_ind = (out_size >= M * DIM + M) ? (out + (size_t)M * DIM) : nullptr;
    vq_argmax_kernel<<<M / BM, NTHREADS, smem_bytes>>>(x, embed, out_ind);

    // 3) Gather quantize rows
    gather_kernel<<<(M * (DIM / 4) + 255) / 256, 256>>>(embed, out, M);

    // 4) Defensive: zero any extra tail of the output buffer
    int written = M * DIM + (out_ind ? M : 0);
    if (out_size > written) {
        int tail = out_size - written;
        fill_kernel<<<(tail + 255) / 256, 256>>>(out, written, out_size);
    }
}

// round 3
// speedup vs baseline: 1.4435x; 1.4435x over previous
#include <cuda_runtime.h>
#include <cuda_bf16.h>
#include <cstdint>
#include <cstddef>

#define DIM   64
#define CBK   4096
#define MAXM  32768
#define KAUG  384            // 6 slices * 64
#define BM    128
#define NT_TILES 32          // 4096 / 128
#define KT_ITERS 12          // 384 / 32

// ---------------------------------------------------------------------------
// Device scratch (static — no dynamic allocation allowed)
// ---------------------------------------------------------------------------
__device__ float g_nhn[CBK];                                     // -0.5*||e||^2
__device__ __align__(256) __nv_bfloat16 g_xaug[(size_t)MAXM * KAUG];
__device__ __align__(256) __nv_bfloat16 g_eaug[(size_t)CBK * KAUG];

// ---------------------------------------------------------------------------
// Small PTX helpers (base sm_103 features only: cp.async / ldmatrix / mma.sync)
// ---------------------------------------------------------------------------
__device__ __forceinline__ uint32_t smem_u32(const void* p) {
    uint32_t a;
    asm("{ .reg .u64 t; cvta.to.shared.u64 t, %1; cvt.u32.u64 %0, t; }"
        : "=r"(a) : "l"(p));
    return a;
}
__device__ __forceinline__ void cp16(uint32_t dst, const void* src) {
    asm volatile("cp.async.cg.shared.global [%0], [%1], 16;" :: "r"(dst), "l"(src));
}
__device__ __forceinline__ void cp_commit() {
    asm volatile("cp.async.commit_group;");
}
__device__ __forceinline__ void cp_wait0() {
    asm volatile("cp.async.wait_group 0;" ::: "memory");
}
__device__ __forceinline__ void ldsm4(uint32_t* r, uint32_t addr) {
    asm volatile("ldmatrix.sync.aligned.m8n8.x4.shared.b16 {%0,%1,%2,%3}, [%4];"
                 : "=r"(r[0]), "=r"(r[1]), "=r"(r[2]), "=r"(r[3]) : "r"(addr));
}
__device__ __forceinline__ void ldsm2(uint32_t* r, uint32_t addr) {
    asm volatile("ldmatrix.sync.aligned.m8n8.x2.shared.b16 {%0,%1}, [%2];"
                 : "=r"(r[0]), "=r"(r[1]) : "r"(addr));
}
__device__ __forceinline__ void hmma(float* d, const uint32_t* a, const uint32_t* b) {
    asm volatile("mma.sync.aligned.m16n8k16.row.col.f32.bf16.bf16.f32 "
                 "{%0,%1,%2,%3}, {%4,%5,%6,%7}, {%8,%9}, {%0,%1,%2,%3};"
                 : "+f"(d[0]), "+f"(d[1]), "+f"(d[2]), "+f"(d[3])
                 : "r"(a[0]), "r"(a[1]), "r"(a[2]), "r"(a[3]),
                   "r"(b[0]), "r"(b[1]));
}

// ---------------------------------------------------------------------------
// Split fp32 -> (h1,h2,h3) bf16 (24 significand bits total), build augmented
// K=384 rows:  X slices [h1,h1,h2,h1,h3,h2] ; E slices [e1,e2,e1,e3,e1,e2]
// so  X_aug . E_aug = h1e1+h1e2+h2e1+h1e3+h3e1+h2e2  (residual ~2^-24).
// ---------------------------------------------------------------------------
__device__ __forceinline__ void split8(float4 lo, float4 hi, uint4* h) {
    float v[8] = {lo.x, lo.y, lo.z, lo.w, hi.x, hi.y, hi.z, hi.w};
    union U { unsigned short s[8]; uint4 u; } u1, u2, u3;
#pragma unroll
    for (int k = 0; k < 8; k++) {
        float a = v[k];
        __nv_bfloat16 b1 = __float2bfloat16(a);
        float r1 = a - __bfloat162float(b1);
        __nv_bfloat16 b2 = __float2bfloat16(r1);
        float r2 = r1 - __bfloat162float(b2);
        __nv_bfloat16 b3 = __float2bfloat16(r2);
        u1.s[k] = *reinterpret_cast<unsigned short*>(&b1);
        u2.s[k] = *reinterpret_cast<unsigned short*>(&b2);
        u3.s[k] = *reinterpret_cast<unsigned short*>(&b3);
    }
    h[0] = u1.u; h[1] = u2.u; h[2] = u3.u;
}

__global__ void split_kernel(const float* __restrict__ x,
                             const float* __restrict__ e, int M) {
    const int gid = blockIdx.x * blockDim.x + threadIdx.x;
    if (gid < M * 8) {
        int row = gid >> 3, c8 = gid & 7;
        const float4* p = reinterpret_cast<const float4*>(x + (size_t)row * DIM + c8 * 8);
        uint4 h[3];
        split8(p[0], p[1], h);
        __nv_bfloat16* dst = g_xaug + (size_t)row * KAUG + c8 * 8;
        const int xs[6] = {0, 0, 1, 0, 2, 1};
#pragma unroll
        for (int s = 0; s < 6; s++)
            *reinterpret_cast<uint4*>(dst + s * DIM) = h[xs[s]];
    }
    if (gid < CBK * 8) {
        int row = gid >> 3, c8 = gid & 7;
        const float4* p = reinterpret_cast<const float4*>(e + (size_t)row * DIM + c8 * 8);
        uint4 h[3];
        split8(p[0], p[1], h);
        __nv_bfloat16* dst = g_eaug + (size_t)row * KAUG + c8 * 8;
        const int es[6] = {0, 1, 0, 2, 0, 1};
#pragma unroll
        for (int s = 0; s < 6; s++)
            *reinterpret_cast<uint4*>(dst + s * DIM) = h[es[s]];
    }
}

// -0.5*||e||^2 (4 threads per codebook row)
__global__ void hn_kernel(const float* __restrict__ e) {
    int tid = blockIdx.x * blockDim.x + threadIdx.x;
    if (tid < CBK * 4) {
        int row = tid >> 2, p = tid & 3;
        const float4* v = reinterpret_cast<const float4*>(e + (size_t)row * DIM) + p * 4;
        float s = 0.f;
#pragma unroll
        for (int i = 0; i < 4; i++) {
            float4 q = v[i];
            s += q.x * q.x + q.y * q.y + q.z * q.z + q.w * q.w;
        }
        s += __shfl_xor_sync(0xffffffffu, s, 1);
        s += __shfl_xor_sync(0xffffffffu, s, 2);
        if (p == 0) g_nhn[row] = -0.5f * s;
    }
}

// ---------------------------------------------------------------------------
// Main kernel: bf16 mma.sync GEMM (128 rows x 4096 codes x K=384) with
// running in-register argmax, fused index write + gather.
// SMEM: A resident 96KB (swizzled), B double-buffered 2x8KB (swizzled).
// 8 warps: wm = wid&1 (64-row half), wn = wid>>1 (32-col quarter).
// ---------------------------------------------------------------------------
#define SMEM_A_BYTES 98304
#define SMEM_B_BYTES 16384
#define SMEM_TOTAL   (SMEM_A_BYTES + SMEM_B_BYTES)

__global__ __launch_bounds__(256, 2)
void vq_mma_kernel(const float* __restrict__ embed,
                   float* __restrict__ outq,
                   float* __restrict__ out_ind) {
    extern __shared__ __align__(128) char smem[];
    const uint32_t As_u = smem_u32(smem);
    const uint32_t Bs_u = As_u + SMEM_A_BYTES;

    const int tid  = threadIdx.x;
    const int lane = tid & 31, wid = tid >> 5;
    const int wm = wid & 1, wn = wid >> 1;
    const int g = lane >> 2, tig = lane & 3;
    const int mtile = blockIdx.x;

    // ---- Prologue: A tile (128 x 384 bf16) via cp.async, swizzled ---------
    const __nv_bfloat16* xa = g_xaug + (size_t)mtile * BM * KAUG;
#pragma unroll
    for (int i = 0; i < 24; i++) {
        int idx = tid + i * 256;          // 6144 16B chunks
        int row = idx / 48, c = idx % 48;
        uint32_t dst = As_u + row * 768 + ((c ^ (row & 7)) << 4);
        cp16(dst, xa + (size_t)row * KAUG + c * 8);
    }
    cp_commit();

    // ---- First B stage (nt=0, kt=0) ---------------------------------------
    {
        const __nv_bfloat16* eb = g_eaug;  // nt=0, kt=0
#pragma unroll
        for (int i = 0; i < 2; i++) {
            int idx = tid + i * 256;      // 512 chunks (128 rows x 64B)
            int row = idx >> 2, c = idx & 3;
            uint32_t dst = Bs_u + row * 64 + ((c ^ ((row >> 1) & 3)) << 4);
            cp16(dst, eb + (size_t)row * KAUG + c * 8);
        }
        cp_commit();
    }

    // Precomputed ldmatrix addressing
    uint32_t aBase[4];
#pragma unroll
    for (int mi = 0; mi < 4; mi++)
        aBase[mi] = As_u + (wm * 64 + mi * 16 + (lane & 15)) * 768;
    const uint32_t amask = (lane & 7) << 4;
    const int     asel  = lane >> 4;               // chunk select 0/1
    uint32_t bOff[4];
#pragma unroll
    for (int ni = 0; ni < 4; ni++)
        bOff[ni] = (wn * 32 + ni * 8 + (lane & 7)) * 64;
    const uint32_t bmask = (((lane & 7) >> 1) & 3) << 4;
    const int     bsel  = (lane >> 3) & 1;

    float best[8];
    int   bidx[8];
#pragma unroll
    for (int s = 0; s < 8; s++) { best[s] = -3.402823466e38f; bidx[s] = 0; }

    cp_wait0();
    __syncthreads();

    // ---- Mainloop over 32 code tiles --------------------------------------
    for (int nt = 0; nt < NT_TILES; nt++) {
        float acc[4][4][4];
#pragma unroll
        for (int mi = 0; mi < 4; mi++)
#pragma unroll
            for (int ni = 0; ni < 4; ni++)
#pragma unroll
                for (int r = 0; r < 4; r++) acc[mi][ni][r] = 0.f;

        for (int kt = 0; kt < KT_ITERS; kt++) {
            const int it  = nt * KT_ITERS + kt;
            const int cur = it & 1;

            // prefetch next B stage
            if (it + 1 < NT_TILES * KT_ITERS) {
                const int nit = it + 1;
                const int nnt = nit / KT_ITERS, nkt = nit % KT_ITERS;
                const __nv_bfloat16* eb =
                    g_eaug + (size_t)nnt * BM * KAUG + nkt * 32;
                const uint32_t sbase = Bs_u + (cur ^ 1) * 8192;
#pragma unroll
                for (int i = 0; i < 2; i++) {
                    int idx = tid + i * 256;
                    int row = idx >> 2, c = idx & 3;
                    uint32_t dst = sbase + row * 64 + ((c ^ ((row >> 1) & 3)) << 4);
                    cp16(dst, eb + (size_t)row * KAUG + c * 8);
                }
                cp_commit();
            }

            // compute current stage (BK=32 -> 2 k16 steps)
            const uint32_t bstage = Bs_u + cur * 8192;
#pragma unroll
            for (int ks = 0; ks < 2; ks++) {
                uint32_t a[4][4];
                const int ca = kt * 4 + ks * 2 + asel;
                const uint32_t aoff = ((uint32_t)ca << 4) ^ amask;
#pragma unroll
                for (int mi = 0; mi < 4; mi++) ldsm4(a[mi], aBase[mi] + aoff);

                uint32_t b[4][2];
                const int cb = ks * 2 + bsel;
                const uint32_t boff = ((uint32_t)cb << 4) ^ bmask;
#pragma unroll
                for (int ni = 0; ni < 4; ni++) ldsm2(b[ni], bstage + bOff[ni] + boff);

#pragma unroll
                for (int mi = 0; mi < 4; mi++)
#pragma unroll
                    for (int ni = 0; ni < 4; ni++)
                        hmma(acc[mi][ni], a[mi], b[ni]);
            }

            cp_wait0();
            __syncthreads();
        }

        // ---- Fold this 128-col tile into the running argmax ---------------
        const int colb = nt * 128 + wn * 32 + tig * 2;
#pragma unroll
        for (int ni = 0; ni < 4; ni++) {
            const int c0 = colb + ni * 8;
            float2 nh = *reinterpret_cast<const float2*>(&g_nhn[c0]);
#pragma unroll
            for (int mi = 0; mi < 4; mi++) {
                float s0 = acc[mi][ni][0] + nh.x;
                float s1 = acc[mi][ni][1] + nh.y;
                float s2 = acc[mi][ni][2] + nh.x;
                float s3 = acc[mi][ni][3] + nh.y;
                int lo = mi * 2, hi = mi * 2 + 1;
                if (s0 > best[lo]) { best[lo] = s0; bidx[lo] = c0; }
                if (s1 > best[lo]) { best[lo] = s1; bidx[lo] = c0 + 1; }
                if (s2 > best[hi]) { best[hi] = s2; bidx[hi] = c0; }
                if (s3 > best[hi]) { best[hi] = s3; bidx[hi] = c0 + 1; }
            }
        }
    }

    // ---- Reduce: quad (tig) via shuffle, then 4 wn warps via SMEM ---------
#pragma unroll
    for (int s = 0; s < 8; s++) {
#pragma unroll
        for (int d = 1; d < 4; d <<= 1) {
            float ov = __shfl_xor_sync(0xffffffffu, best[s], d);
            int   oi = __shfl_xor_sync(0xffffffffu, bidx[s], d);
            if (ov > best[s] || (ov == best[s] && oi < bidx[s])) {
                best[s] = ov; bidx[s] = oi;
            }
        }
    }
    __syncthreads();   // done with B buffers; reuse as reduction scratch
    float* redv = reinterpret_cast<float*>(smem + SMEM_A_BYTES);
    int*   redi = reinterpret_cast<int*>(smem + SMEM_A_BYTES + 2048);
    if (tig == 0) {
#pragma unroll
        for (int s = 0; s < 8; s++) {
            int row = wm * 64 + (s >> 1) * 16 + g + (s & 1) * 8;
            redv[row * 4 + wn] = best[s];
            redi[row * 4 + wn] = bidx[s];
        }
    }
    __syncthreads();

    if (tid < BM) {
        float bv = redv[tid * 4];
        int   bi = redi[tid * 4];
#pragma unroll
        for (int j = 1; j < 4; j++) {
            float v  = redv[tid * 4 + j];
            int   ii = redi[tid * 4 + j];
            if (v > bv || (v == bv && ii < bi)) { bv = v; bi = ii; }
        }
        const int grow = mtile * BM + tid;
        if (out_ind) out_ind[grow] = (float)bi;
        const float4* e4 = reinterpret_cast<const float4*>(embed + (size_t)bi * DIM);
        float4* o4 = reinterpret_cast<float4*>(outq + (size_t)grow * DIM);
#pragma unroll
        for (int i = 0; i < DIM / 4; i++) o4[i] = e4[i];
    }
}

// Defensive tail fill.
__global__ void fill_kernel(float* __restrict__ out, int start, int end) {
    int i = start + blockIdx.x * blockDim.x + threadIdx.x;
    if (i < end) out[i] = 0.f;
}

// ---------------------------------------------------------------------------
extern "C" void kernel_launch(void* const* d_in, const int* in_sizes, int n_in,
                              void* d_out, int out_size) {
    const float* x     = (const float*)d_in[0];   // [8,4096,64] f32
    const float* embed = (const float*)d_in[1];   // [4096,64]   f32
    float* out = (float*)d_out;

    const int M = in_sizes[0] / DIM;              // 32768

    int nthr = M * 8 > CBK * 8 ? M * 8 : CBK * 8;
    split_kernel<<<(nthr + 255) / 256, 256>>>(x, embed, M);
    hn_kernel<<<(CBK * 4 + 255) / 256, 256>>>(embed);

    cudaFuncSetAttribute(vq_mma_kernel,
                         cudaFuncAttributeMaxDynamicSharedMemorySize, SMEM_TOTAL);

    float* oind = (out_size >= M * DIM + M) ? (out + (size_t)M * DIM) : nullptr;
    vq_mma_kernel<<<M / BM, 256, SMEM_TOTAL>>>(embed, out, oind);

    int written = M * DIM + (oind ? M : 0);
    if (out_size > written) {
        int tail = out_size - written;
        fill_kernel<<<(tail + 255) / 256, 256>>>(out, written, out_size);
    }
}

// round 4
// speedup vs baseline: 1.6119x; 1.1166x over previous
#include <cuda_runtime.h>
#include <cuda_bf16.h>
#include <cstdint>
#include <cstddef>

#define DIM   64
#define CBK   4096
#define MAXM  32768
#define KU    192            // unique slices: [h1|h2|h3] / [e1|e2|e3]
#define BM    128
#define NT_TILES 32          // 4096 / 128
#define NSTAGES  96          // 32 nt * 3 e-slices

// ---------------------------------------------------------------------------
// Device scratch (static — no dynamic allocation allowed)
// ---------------------------------------------------------------------------
__device__ float g_nhn[CBK];                                   // -0.5*||e||^2
__device__ __align__(256) __nv_bfloat16 g_xs[(size_t)MAXM * KU];
__device__ __align__(256) __nv_bfloat16 g_es[(size_t)CBK * KU];

// ---------------------------------------------------------------------------
// PTX helpers (base sm_103 features only)
// ---------------------------------------------------------------------------
__device__ __forceinline__ uint32_t smem_u32(const void* p) {
    uint32_t a;
    asm("{ .reg .u64 t; cvta.to.shared.u64 t, %1; cvt.u32.u64 %0, t; }"
        : "=r"(a) : "l"(p));
    return a;
}
__device__ __forceinline__ void cp16(uint32_t dst, const void* src) {
    asm volatile("cp.async.cg.shared.global [%0], [%1], 16;" :: "r"(dst), "l"(src));
}
__device__ __forceinline__ void cp_commit() {
    asm volatile("cp.async.commit_group;");
}
#define CP_WAIT(n) asm volatile("cp.async.wait_group %0;" :: "n"(n) : "memory")
__device__ __forceinline__ void ldsm4(uint32_t* r, uint32_t addr) {
    asm volatile("ldmatrix.sync.aligned.m8n8.x4.shared.b16 {%0,%1,%2,%3}, [%4];"
                 : "=r"(r[0]), "=r"(r[1]), "=r"(r[2]), "=r"(r[3]) : "r"(addr));
}
__device__ __forceinline__ void ldsm2(uint32_t* r, uint32_t addr) {
    asm volatile("ldmatrix.sync.aligned.m8n8.x2.shared.b16 {%0,%1}, [%2];"
                 : "=r"(r[0]), "=r"(r[1]) : "r"(addr));
}
__device__ __forceinline__ void hmma(float* d, const uint32_t* a, const uint32_t* b) {
    asm volatile("mma.sync.aligned.m16n8k16.row.col.f32.bf16.bf16.f32 "
                 "{%0,%1,%2,%3}, {%4,%5,%6,%7}, {%8,%9}, {%0,%1,%2,%3};"
                 : "+f"(d[0]), "+f"(d[1]), "+f"(d[2]), "+f"(d[3])
                 : "r"(a[0]), "r"(a[1]), "r"(a[2]), "r"(a[3]),
                   "r"(b[0]), "r"(b[1]));
}

// ---------------------------------------------------------------------------
// Split fp32 -> (h1,h2,h3) bf16.  Score = sum of 6 HMMA term-products:
//   h1e1 + h1e2 + h2e1 + h1e3 + h3e1 + h2e2   (residual ~2^-24 relative)
// ---------------------------------------------------------------------------
__device__ __forceinline__ void split8(float4 lo, float4 hi, uint4* h) {
    float v[8] = {lo.x, lo.y, lo.z, lo.w, hi.x, hi.y, hi.z, hi.w};
    union U { unsigned short s[8]; uint4 u; } u1, u2, u3;
#pragma unroll
    for (int k = 0; k < 8; k++) {
        float a = v[k];
        __nv_bfloat16 b1 = __float2bfloat16(a);
        float r1 = a - __bfloat162float(b1);
        __nv_bfloat16 b2 = __float2bfloat16(r1);
        float r2 = r1 - __bfloat162float(b2);
        __nv_bfloat16 b3 = __float2bfloat16(r2);
        u1.s[k] = *reinterpret_cast<unsigned short*>(&b1);
        u2.s[k] = *reinterpret_cast<unsigned short*>(&b2);
        u3.s[k] = *reinterpret_cast<unsigned short*>(&b3);
    }
    h[0] = u1.u; h[1] = u2.u; h[2] = u3.u;
}

__global__ void split_kernel(const float* __restrict__ x,
                             const float* __restrict__ e, int M) {
    const int gid = blockIdx.x * blockDim.x + threadIdx.x;
    if (gid < M * 8) {
        int row = gid >> 3, c8 = gid & 7;
        const float4* p = reinterpret_cast<const float4*>(x + (size_t)row * DIM + c8 * 8);
        uint4 h[3];
        split8(p[0], p[1], h);
        __nv_bfloat16* dst = g_xs + (size_t)row * KU + c8 * 8;
#pragma unroll
        for (int s = 0; s < 3; s++)
            *reinterpret_cast<uint4*>(dst + s * DIM) = h[s];
    }
    if (gid < CBK * 8) {
        int row = gid >> 3, c8 = gid & 7;
        const float4* p = reinterpret_cast<const float4*>(e + (size_t)row * DIM + c8 * 8);
        uint4 h[3];
        split8(p[0], p[1], h);
        __nv_bfloat16* dst = g_es + (size_t)row * KU + c8 * 8;
#pragma unroll
        for (int s = 0; s < 3; s++)
            *reinterpret_cast<uint4*>(dst + s * DIM) = h[s];
    }
}

// -0.5*||e||^2 (4 threads per codebook row)
__global__ void hn_kernel(const float* __restrict__ e) {
    int tid = blockIdx.x * blockDim.x + threadIdx.x;
    if (tid < CBK * 4) {
        int row = tid >> 2, p = tid & 3;
        const float4* v = reinterpret_cast<const float4*>(e + (size_t)row * DIM) + p * 4;
        float s = 0.f;
#pragma unroll
        for (int i = 0; i < 4; i++) {
            float4 q = v[i];
            s += q.x * q.x + q.y * q.y + q.z * q.z + q.w * q.w;
        }
        s += __shfl_xor_sync(0xffffffffu, s, 1);
        s += __shfl_xor_sync(0xffffffffu, s, 2);
        if (p == 0) g_nhn[row] = -0.5f * s;
    }
}

// ---------------------------------------------------------------------------
// Main kernel.
// SMEM: A 3x16KB resident (unique x-slices, SW-swizzled 128B rows),
//       B ring 4x16KB stages (one (nt, e-slice) tile per stage).
// Stage (nt,s): B slice e_{s+1}; consumed against A slices h1..h_{3-s}.
// cp.async depth-3 pipeline (wait_group 2), one __syncthreads per stage.
// ---------------------------------------------------------------------------
#define SMEM_A  49152
#define SMEM_B  65536
#define SMEM_TOTAL (SMEM_A + SMEM_B)   // 114688 B -> 2 CTAs/SM

template<int TERMS>
__device__ __forceinline__ void compute_stage(
    float (&acc)[4][4][4], const uint32_t* aBase, uint32_t amask, uint32_t asel,
    uint32_t bst, const uint32_t* bOff, uint32_t bmask, uint32_t bsel)
{
#pragma unroll
    for (int ks = 0; ks < 4; ks++) {
        uint32_t b[4][2];
        const uint32_t boff = (((uint32_t)(ks * 2) + bsel) << 4) ^ bmask;
#pragma unroll
        for (int ni = 0; ni < 4; ni++) ldsm2(b[ni], bst + bOff[ni] + boff);
        const uint32_t aoff = (((uint32_t)(ks * 2) + asel) << 4) ^ amask;
#pragma unroll
        for (int t = 0; t < TERMS; t++) {
            uint32_t a[4][4];
#pragma unroll
            for (int mi = 0; mi < 4; mi++)
                ldsm4(a[mi], aBase[mi] + t * 16384 + aoff);
#pragma unroll
            for (int mi = 0; mi < 4; mi++)
#pragma unroll
                for (int ni = 0; ni < 4; ni++)
                    hmma(acc[mi][ni], a[mi], b[ni]);
        }
    }
}

__global__ __launch_bounds__(256, 2)
void vq_mma_kernel(const float* __restrict__ embed,
                   float* __restrict__ outq,
                   float* __restrict__ out_ind) {
    extern __shared__ __align__(128) char smem[];
    const uint32_t As_u = smem_u32(smem);
    const uint32_t Bs_u = As_u + SMEM_A;

    const int tid  = threadIdx.x;
    const int lane = tid & 31, wid = tid >> 5;
    const int wm = wid & 1, wn = wid >> 1;
    const int g = lane >> 2, tig = lane & 3;
    const int mtile = blockIdx.x;

    // B prefetch helper (16KB stage = 1024 chunks, 4 per thread)
    auto prefetchB = [&](int nt, int s, int slot) {
        const __nv_bfloat16* src = g_es + (size_t)nt * BM * KU + s * DIM;
        const uint32_t dbase = Bs_u + slot * 16384;
#pragma unroll
        for (int i = 0; i < 4; i++) {
            int idx = tid + i * 256;
            int row = idx >> 3, c = idx & 7;
            cp16(dbase + row * 128 + ((c ^ (row & 7)) << 4),
                 src + (size_t)row * KU + c * 8);
        }
    };

    // ---- Prologue: A (3 slices) + first 3 B stages ------------------------
    {
        const __nv_bfloat16* xa = g_xs + (size_t)mtile * BM * KU;
#pragma unroll
        for (int s = 0; s < 3; s++)
#pragma unroll
            for (int i = 0; i < 4; i++) {
                int idx = tid + i * 256;
                int row = idx >> 3, c = idx & 7;
                cp16(As_u + s * 16384 + row * 128 + ((c ^ (row & 7)) << 4),
                     xa + (size_t)row * KU + s * DIM + c * 8);
            }
        prefetchB(0, 0, 0); cp_commit();   // group: A + stage0
        prefetchB(0, 1, 1); cp_commit();
        prefetchB(0, 2, 2); cp_commit();
    }

    // ldmatrix addressing
    uint32_t aBase[4];
#pragma unroll
    for (int mi = 0; mi < 4; mi++)
        aBase[mi] = As_u + (wm * 64 + mi * 16 + (lane & 15)) * 128;
    const uint32_t amask = (lane & 7) << 4;
    const uint32_t asel  = lane >> 4;
    uint32_t bOff[4];
#pragma unroll
    for (int ni = 0; ni < 4; ni++)
        bOff[ni] = (wn * 32 + ni * 8 + (lane & 7)) * 128;
    const uint32_t bmask = (lane & 7) << 4;
    const uint32_t bsel  = (lane >> 3) & 1;

    float best[8];
    int   bidx[8];
#pragma unroll
    for (int s = 0; s < 8; s++) { best[s] = -3.402823466e38f; bidx[s] = 0; }

    float acc[4][4][4];
    int cn = 0, cs = 0;          // current stage (nt, slice)
    int pn = 1, ps = 0;          // prefetch stage = current + 3

    // ---- Mainloop: 96 stages ----------------------------------------------
    for (int si = 0; si < NSTAGES; si++) {
        CP_WAIT(2);
        __syncthreads();
        if (si < NSTAGES - 3) {
            prefetchB(pn, ps, (si + 3) & 3);
            if (++ps == 3) { ps = 0; pn++; }
        }
        cp_commit();

        if (cs == 0) {
#pragma unroll
            for (int mi = 0; mi < 4; mi++)
#pragma unroll
                for (int ni = 0; ni < 4; ni++)
#pragma unroll
                    for (int r = 0; r < 4; r++) acc[mi][ni][r] = 0.f;
        }

        const uint32_t bst = Bs_u + (si & 3) * 16384;
        if (cs == 0)      compute_stage<3>(acc, aBase, amask, asel, bst, bOff, bmask, bsel);
        else if (cs == 1) compute_stage<2>(acc, aBase, amask, asel, bst, bOff, bmask, bsel);
        else              compute_stage<1>(acc, aBase, amask, asel, bst, bOff, bmask, bsel);

        if (cs == 2) {
            // fold this 128-col tile into the running argmax
            const int colb = cn * 128 + wn * 32 + tig * 2;
#pragma unroll
            for (int ni = 0; ni < 4; ni++) {
                const int c0 = colb + ni * 8;
                float2 nh = *reinterpret_cast<const float2*>(&g_nhn[c0]);
#pragma unroll
                for (int mi = 0; mi < 4; mi++) {
                    float s0 = acc[mi][ni][0] + nh.x;
                    float s1 = acc[mi][ni][1] + nh.y;
                    float s2 = acc[mi][ni][2] + nh.x;
                    float s3 = acc[mi][ni][3] + nh.y;
                    int lo = mi * 2, hi = mi * 2 + 1;
                    if (s0 > best[lo]) { best[lo] = s0; bidx[lo] = c0; }
                    if (s1 > best[lo]) { best[lo] = s1; bidx[lo] = c0 + 1; }
                    if (s2 > best[hi]) { best[hi] = s2; bidx[hi] = c0; }
                    if (s3 > best[hi]) { best[hi] = s3; bidx[hi] = c0 + 1; }
                }
            }
            cs = 0; cn++;
        } else {
            cs++;
        }
    }

    // ---- Reduce: quad (tig) via shuffle, then 4 wn warps via SMEM ---------
#pragma unroll
    for (int s = 0; s < 8; s++) {
#pragma unroll
        for (int d = 1; d < 4; d <<= 1) {
            float ov = __shfl_xor_sync(0xffffffffu, best[s], d);
            int   oi = __shfl_xor_sync(0xffffffffu, bidx[s], d);
            if (ov > best[s] || (ov == best[s] && oi < bidx[s])) {
                best[s] = ov; bidx[s] = oi;
            }
        }
    }
    __syncthreads();   // done with B ring; reuse as reduction scratch
    float* redv = reinterpret_cast<float*>(smem + SMEM_A);
    int*   redi = reinterpret_cast<int*>(smem + SMEM_A + 2048);
    if (tig == 0) {
#pragma unroll
        for (int s = 0; s < 8; s++) {
            int row = wm * 64 + (s >> 1) * 16 + g + (s & 1) * 8;
            redv[row * 4 + wn] = best[s];
            redi[row * 4 + wn] = bidx[s];
        }
    }
    __syncthreads();

    if (tid < BM) {
        float bv = redv[tid * 4];
        int   bi = redi[tid * 4];
#pragma unroll
        for (int j = 1; j < 4; j++) {
            float v  = redv[tid * 4 + j];
            int   ii = redi[tid * 4 + j];
            if (v > bv || (v == bv && ii < bi)) { bv = v; bi = ii; }
        }
        const int grow = mtile * BM + tid;
        if (out_ind) out_ind[grow] = (float)bi;
        const float4* e4 = reinterpret_cast<const float4*>(embed + (size_t)bi * DIM);
        float4* o4 = reinterpret_cast<float4*>(outq + (size_t)grow * DIM);
#pragma unroll
        for (int i = 0; i < DIM / 4; i++) o4[i] = e4[i];
    }
}

// Defensive tail fill.
__global__ void fill_kernel(float* __restrict__ out, int start, int end) {
    int i = start + blockIdx.x * blockDim.x + threadIdx.x;
    if (i < end) out[i] = 0.f;
}

// ---------------------------------------------------------------------------
extern "C" void kernel_launch(void* const* d_in, const int* in_sizes, int n_in,
                              void* d_out, int out_size) {
    const float* x     = (const float*)d_in[0];   // [8,4096,64] f32
    const float* embed = (const float*)d_in[1];   // [4096,64]   f32
    float* out = (float*)d_out;

    const int M = in_sizes[0] / DIM;              // 32768

    int nthr = M * 8 > CBK * 8 ? M * 8 : CBK * 8;
    split_kernel<<<(nthr + 255) / 256, 256>>>(x, embed, M);
    hn_kernel<<<(CBK * 4 + 255) / 256, 256>>>(embed);

    cudaFuncSetAttribute(vq_mma_kernel,
                         cudaFuncAttributeMaxDynamicSharedMemorySize, SMEM_TOTAL);

    float* oind = (out_size >= M * DIM + M) ? (out + (size_t)M * DIM) : nullptr;
    vq_mma_kernel<<<M / BM, 256, SMEM_TOTAL>>>(embed, out, oind);

    int written = M * DIM + (oind ? M : 0);
    if (out_size > written) {
        int tail = out_size - written;
        fill_kernel<<<(tail + 255) / 256, 256>>>(out, written, out_size);
    }
}

// round 6
// speedup vs baseline: 2.7393x; 1.6995x over previous
#include <cuda_runtime.h>
#include <cuda_fp16.h>
#include <cstdint>
#include <cstddef>

#define DIM   64
#define CBK   4096
#define MAXM  32768
#define KU    128            // unique slices: [h1|h2] / [e1|e2]  (fp16)
#define BM    128
#define NSTAGES  64          // 32 nt * 2 e-slices

// ---------------------------------------------------------------------------
// Device scratch (static — no dynamic allocation allowed)
// ---------------------------------------------------------------------------
__device__ float g_nhn[CBK];                                   // -0.5*||e||^2
__device__ __align__(256) __half g_xs[(size_t)MAXM * KU];
__device__ __align__(256) __half g_es[(size_t)CBK * KU];

// ---------------------------------------------------------------------------
// PTX helpers (base sm_103 features only)
// ---------------------------------------------------------------------------
__device__ __forceinline__ uint32_t smem_u32(const void* p) {
    uint32_t a;
    asm("{ .reg .u64 t; cvta.to.shared.u64 t, %1; cvt.u32.u64 %0, t; }"
        : "=r"(a) : "l"(p));
    return a;
}
__device__ __forceinline__ void cp16(uint32_t dst, const void* src) {
    asm volatile("cp.async.cg.shared.global [%0], [%1], 16;" :: "r"(dst), "l"(src));
}
__device__ __forceinline__ void cp_commit() {
    asm volatile("cp.async.commit_group;");
}
#define CP_WAIT(n) asm volatile("cp.async.wait_group %0;" :: "n"(n) : "memory")
__device__ __forceinline__ void ldsm4(uint32_t* r, uint32_t addr) {
    asm volatile("ldmatrix.sync.aligned.m8n8.x4.shared.b16 {%0,%1,%2,%3}, [%4];"
                 : "=r"(r[0]), "=r"(r[1]), "=r"(r[2]), "=r"(r[3]) : "r"(addr));
}
__device__ __forceinline__ void ldsm2(uint32_t* r, uint32_t addr) {
    asm volatile("ldmatrix.sync.aligned.m8n8.x2.shared.b16 {%0,%1}, [%2];"
                 : "=r"(r[0]), "=r"(r[1]) : "r"(addr));
}
__device__ __forceinline__ void hmma(float* d, const uint32_t* a, const uint32_t* b) {
    asm volatile("mma.sync.aligned.m16n8k16.row.col.f32.f16.f16.f32 "
                 "{%0,%1,%2,%3}, {%4,%5,%6,%7}, {%8,%9}, {%0,%1,%2,%3};"
                 : "+f"(d[0]), "+f"(d[1]), "+f"(d[2]), "+f"(d[3])
                 : "r"(a[0]), "r"(a[1]), "r"(a[2]), "r"(a[3]),
                   "r"(b[0]), "r"(b[1]));
}

// ---------------------------------------------------------------------------
// Split fp32 -> (h1,h2) fp16 (captures ~22 significand bits).
// Score = h1e1 + h1e2 + h2e1 ; dropped h2e2 ~ 2^-22 relative.
// ---------------------------------------------------------------------------
__device__ __forceinline__ void split8(float4 lo, float4 hi, uint4* h) {
    float v[8] = {lo.x, lo.y, lo.z, lo.w, hi.x, hi.y, hi.z, hi.w};
    union U { unsigned short s[8]; uint4 u; } u1, u2;
#pragma unroll
    for (int k = 0; k < 8; k++) {
        float a = v[k];
        __half b1 = __float2half_rn(a);
        float r1 = a - __half2float(b1);
        __half b2 = __float2half_rn(r1);
        u1.s[k] = *reinterpret_cast<unsigned short*>(&b1);
        u2.s[k] = *reinterpret_cast<unsigned short*>(&b2);
    }
    h[0] = u1.u; h[1] = u2.u;
}

__global__ void split_kernel(const float* __restrict__ x,
                             const float* __restrict__ e, int M) {
    const int gid = blockIdx.x * blockDim.x + threadIdx.x;
    if (gid < M * 8) {
        int row = gid >> 3, c8 = gid & 7;
        const float4* p = reinterpret_cast<const float4*>(x + (size_t)row * DIM + c8 * 8);
        uint4 h[2];
        split8(p[0], p[1], h);
        __half* dst = g_xs + (size_t)row * KU + c8 * 8;
        *reinterpret_cast<uint4*>(dst)       = h[0];
        *reinterpret_cast<uint4*>(dst + DIM) = h[1];
    }
    if (gid < CBK * 8) {
        int row = gid >> 3, c8 = gid & 7;
        const float4* p = reinterpret_cast<const float4*>(e + (size_t)row * DIM + c8 * 8);
        uint4 h[2];
        split8(p[0], p[1], h);
        __half* dst = g_es + (size_t)row * KU + c8 * 8;
        *reinterpret_cast<uint4*>(dst)       = h[0];
        *reinterpret_cast<uint4*>(dst + DIM) = h[1];
    }
}

// -0.5*||e||^2 (4 threads per codebook row)
__global__ void hn_kernel(const float* __restrict__ e) {
    int tid = blockIdx.x * blockDim.x + threadIdx.x;
    if (tid < CBK * 4) {
        int row = tid >> 2, p = tid & 3;
        const float4* v = reinterpret_cast<const float4*>(e + (size_t)row * DIM) + p * 4;
        float s = 0.f;
#pragma unroll
        for (int i = 0; i < 4; i++) {
            float4 q = v[i];
            s += q.x * q.x + q.y * q.y + q.z * q.z + q.w * q.w;
        }
        s += __shfl_xor_sync(0xffffffffu, s, 1);
        s += __shfl_xor_sync(0xffffffffu, s, 2);
        if (p == 0) g_nhn[row] = -0.5f * s;
    }
}

// ---------------------------------------------------------------------------
// Main kernel.
// SMEM: A 2x16KB resident (x slices h1,h2; swizzled 128B rows),
//       B ring 4x16KB stages (one (nt, e-slice) tile per stage).
// Stage (nt,0)=e1: consumed vs h1 and h2.  Stage (nt,1)=e2: consumed vs h1.
// cp.async depth-3 pipeline (wait_group 2), one __syncthreads per stage.
// ---------------------------------------------------------------------------
#define SMEM_A  32768
#define SMEM_B  65536
#define SMEM_TOTAL (SMEM_A + SMEM_B)   // 98304 B -> 2 CTAs/SM

template<int TERMS>
__device__ __forceinline__ void compute_stage(
    float (&acc)[4][4][4], const uint32_t* aBase, uint32_t amask, uint32_t asel,
    uint32_t bst, const uint32_t* bOff, uint32_t bmask, uint32_t bsel)
{
#pragma unroll
    for (int ks = 0; ks < 4; ks++) {
        uint32_t b[4][2];
        const uint32_t boff = (((uint32_t)(ks * 2) + bsel) << 4) ^ bmask;
#pragma unroll
        for (int ni = 0; ni < 4; ni++) ldsm2(b[ni], bst + bOff[ni] + boff);
        const uint32_t aoff = (((uint32_t)(ks * 2) + asel) << 4) ^ amask;
#pragma unroll
        for (int t = 0; t < TERMS; t++) {
            uint32_t a[4][4];
#pragma unroll
            for (int mi = 0; mi < 4; mi++)
                ldsm4(a[mi], aBase[mi] + t * 16384 + aoff);
#pragma unroll
            for (int mi = 0; mi < 4; mi++)
#pragma unroll
                for (int ni = 0; ni < 4; ni++)
                    hmma(acc[mi][ni], a[mi], b[ni]);
        }
    }
}

__global__ __launch_bounds__(256, 2)
void vq_mma_kernel(const float* __restrict__ embed,
                   float* __restrict__ outq,
                   float* __restrict__ out_ind) {
    extern __shared__ __align__(128) char smem[];
    const uint32_t As_u = smem_u32(smem);
    const uint32_t Bs_u = As_u + SMEM_A;

    const int tid  = threadIdx.x;
    const int lane = tid & 31, wid = tid >> 5;
    const int wm = wid & 1, wn = wid >> 1;
    const int g = lane >> 2, tig = lane & 3;
    const int mtile = blockIdx.x;

    // B prefetch helper (16KB stage = 1024 chunks, 4 per thread)
    auto prefetchB = [&](int nt, int s, int slot) {
        const __half* src = g_es + (size_t)nt * BM * KU + s * DIM;
        const uint32_t dbase = Bs_u + slot * 16384;
#pragma unroll
        for (int i = 0; i < 4; i++) {
            int idx = tid + i * 256;
            int row = idx >> 3, c = idx & 7;
            cp16(dbase + row * 128 + ((c ^ (row & 7)) << 4),
                 src + (size_t)row * KU + c * 8);
        }
    };

    // ---- Prologue: A (2 slices) + first 3 B stages ------------------------
    {
        const __half* xa = g_xs + (size_t)mtile * BM * KU;
#pragma unroll
        for (int s = 0; s < 2; s++)
#pragma unroll
            for (int i = 0; i < 4; i++) {
                int idx = tid + i * 256;
                int row = idx >> 3, c = idx & 7;
                cp16(As_u + s * 16384 + row * 128 + ((c ^ (row & 7)) << 4),
                     xa + (size_t)row * KU + s * DIM + c * 8);
            }
        prefetchB(0, 0, 0); cp_commit();   // group: A + stage0
        prefetchB(0, 1, 1); cp_commit();
        prefetchB(1, 0, 2); cp_commit();
    }

    // ldmatrix addressing
    uint32_t aBase[4];
#pragma unroll
    for (int mi = 0; mi < 4; mi++)
        aBase[mi] = As_u + (wm * 64 + mi * 16 + (lane & 15)) * 128;
    const uint32_t amask = (lane & 7) << 4;
    const uint32_t asel  = lane >> 4;
    uint32_t bOff[4];
#pragma unroll
    for (int ni = 0; ni < 4; ni++)
        bOff[ni] = (wn * 32 + ni * 8 + (lane & 7)) * 128;
    const uint32_t bmask = (lane & 7) << 4;
    const uint32_t bsel  = (lane >> 3) & 1;

    float best[8];
    int   bidx[8];
#pragma unroll
    for (int s = 0; s < 8; s++) { best[s] = -3.402823466e38f; bidx[s] = 0; }

    float acc[4][4][4];
    int pn = 1, ps = 1;          // prefetch stage = current + 3

    // ---- Mainloop: 64 stages ----------------------------------------------
    for (int si = 0; si < NSTAGES; si++) {
        const int cs = si & 1, cn = si >> 1;
        CP_WAIT(2);
        __syncthreads();
        if (si < NSTAGES - 3) {
            prefetchB(pn, ps, (si + 3) & 3);
            if (++ps == 2) { ps = 0; pn++; }
        }
        cp_commit();

        if (cs == 0) {
#pragma unroll
            for (int mi = 0; mi < 4; mi++)
#pragma unroll
                for (int ni = 0; ni < 4; ni++)
#pragma unroll
                    for (int r = 0; r < 4; r++) acc[mi][ni][r] = 0.f;
        }

        const uint32_t bst = Bs_u + (si & 3) * 16384;
        if (cs == 0) compute_stage<2>(acc, aBase, amask, asel, bst, bOff, bmask, bsel);
        else         compute_stage<1>(acc, aBase, amask, asel, bst, bOff, bmask, bsel);

        if (cs == 1) {
            // fold this 128-col tile into the running argmax
            const int colb = cn * 128 + wn * 32 + tig * 2;
#pragma unroll
            for (int ni = 0; ni < 4; ni++) {
                const int c0 = colb + ni * 8;
                float2 nh = *reinterpret_cast<const float2*>(&g_nhn[c0]);
#pragma unroll
                for (int mi = 0; mi < 4; mi++) {
                    float s0 = acc[mi][ni][0] + nh.x;
                    float s1 = acc[mi][ni][1] + nh.y;
                    float s2 = acc[mi][ni][2] + nh.x;
                    float s3 = acc[mi][ni][3] + nh.y;
                    int lo = mi * 2, hi = mi * 2 + 1;
                    if (s0 > best[lo]) { best[lo] = s0; bidx[lo] = c0; }
                    if (s1 > best[lo]) { best[lo] = s1; bidx[lo] = c0 + 1; }
                    if (s2 > best[hi]) { best[hi] = s2; bidx[hi] = c0; }
                    if (s3 > best[hi]) { best[hi] = s3; bidx[hi] = c0 + 1; }
                }
            }
        }
    }

    // ---- Reduce: quad (tig) via shuffle, then 4 wn warps via SMEM ---------
#pragma unroll
    for (int s = 0; s < 8; s++) {
#pragma unroll
        for (int d = 1; d < 4; d <<= 1) {
            float ov = __shfl_xor_sync(0xffffffffu, best[s], d);
            int   oi = __shfl_xor_sync(0xffffffffu, bidx[s], d);
            if (ov > best[s] || (ov == best[s] && oi < bidx[s])) {
                best[s] = ov; bidx[s] = oi;
            }
        }
    }
    __syncthreads();   // done with B ring; reuse as reduction scratch
    float* redv = reinterpret_cast<float*>(smem + SMEM_A);
    int*   redi = reinterpret_cast<int*>(smem + SMEM_A + 2048);
    if (tig == 0) {
#pragma unroll
        for (int s = 0; s < 8; s++) {
            int row = wm * 64 + (s >> 1) * 16 + g + (s & 1) * 8;
            redv[row * 4 + wn] = best[s];
            redi[row * 4 + wn] = bidx[s];
        }
    }
    __syncthreads();

    if (tid < BM) {
        float bv = redv[tid * 4];
        int   bi = redi[tid * 4];
#pragma unroll
        for (int j = 1; j < 4; j++) {
            float v  = redv[tid * 4 + j];
            int   ii = redi[tid * 4 + j];
            if (v > bv || (v == bv && ii < bi)) { bv = v; bi = ii; }
        }
        const int grow = mtile * BM + tid;
        if (out_ind) out_ind[grow] = (float)bi;
        const float4* e4 = reinterpret_cast<const float4*>(embed + (size_t)bi * DIM);
        float4* o4 = reinterpret_cast<float4*>(outq + (size_t)grow * DIM);
#pragma unroll
        for (int i = 0; i < DIM / 4; i++) o4[i] = e4[i];
    }
}

// Defensive tail fill.
__global__ void fill_kernel(float* __restrict__ out, int start, int end) {
    int i = start + blockIdx.x * blockDim.x + threadIdx.x;
    if (i < end) out[i] = 0.f;
}

// ---------------------------------------------------------------------------
extern "C" void kernel_launch(void* const* d_in, const int* in_sizes, int n_in,
                              void* d_out, int out_size) {
    const float* x     = (const float*)d_in[0];   // [8,4096,64] f32
    const float* embed = (const float*)d_in[1];   // [4096,64]   f32
    float* out = (float*)d_out;

    const int M = in_sizes[0] / DIM;              // 32768

    int nthr = M * 8 > CBK * 8 ? M * 8 : CBK * 8;
    split_kernel<<<(nthr + 255) / 256, 256>>>(x, embed, M);
    hn_kernel<<<(CBK * 4 + 255) / 256, 256>>>(embed);

    cudaFuncSetAttribute(vq_mma_kernel,
                         cudaFuncAttributeMaxDynamicSharedMemorySize, SMEM_TOTAL);

    float* oind = (out_size >= M * DIM + M) ? (out + (size_t)M * DIM) : nullptr;
    vq_mma_kernel<<<M / BM, 256, SMEM_TOTAL>>>(embed, out, oind);

    int written = M * DIM + (oind ? M : 0);
    if (out_size > written) {
        int tail = out_size - written;
        fill_kernel<<<(tail + 255) / 256, 256>>>(out, written, out_size);
    }
}